// round 10
// baseline (speedup 1.0000x reference)
#include <cuda_runtime.h>
#include <cuda_bf16.h>
#include <math.h>

#define B_SZ   16
#define C_IN   64
#define HH     256
#define WW     256
#define CKK    576
#define FC_DIM 512
#define IMG_PIX (HH * WW)
#define N_IMG  (B_SZ * C_IN)
#define FOUT_ELEMS ((size_t)N_IMG * IMG_PIX)

#define MLP_BLOCKS 81   // < 148 SMs -> all resident; spin barriers safe

// Partial buffers (deterministic fixed-order summation)
__device__ float g_p1[8][B_SZ * CKK];   // layer1 partials per 64-i-chunk (ic0 includes b1)
__device__ float g_p2[9][B_SZ * CKK];   // layer2 partials per 64-i-chunk (ic0 includes b2)
__device__ float g_kw[B_SZ * CKK];      // softmaxed kernel weights
__device__ unsigned int g_c1, g_c2, g_c3;   // barrier counters (zero-init)

__device__ __forceinline__ void grid_barrier(unsigned int* cnt, unsigned int* rst) {
    __threadfence();
    __syncthreads();
    if (threadIdx.x == 0) {
        unsigned int old = atomicAdd(cnt, 1u);
        if (rst && old == MLP_BLOCKS - 1u) *rst = 0u;
        while (__ldcg(cnt) < MLP_BLOCKS) __nanosleep(20);
    }
    __syncthreads();
    __threadfence();
}

// ---------------------------------------------------------------------------
// One-kernel MLP (verbatim from passing Round-8 version, plus PDL trigger).
// 81 blocks x 256 threads, 3 barrier-separated phases.
// ---------------------------------------------------------------------------
__global__ __launch_bounds__(256) void EKG_mlp_one(
    const float* __restrict__ Fc,
    const float* __restrict__ W1, const float* __restrict__ b1,
    const float* __restrict__ W2, const float* __restrict__ b2,
    float* __restrict__ kw_tail, int write_tail)
{
    // Allow the dependent conv grid to launch right away (PDL trigger).
    asm volatile("griddepcontrol.launch_dependents;" ::: "memory");

    __shared__ float sfc[16 * 64];        // [b][il] input slice
    __shared__ float srd[4 * 64 * 16];    // [ty][j_local][b] reduction buffer
    __shared__ float red[8];
    __shared__ float bcast;

    const int bid = blockIdx.x;
    const int tid = threadIdx.x;
    const int tx  = tid & 63;
    const int ty  = tid >> 6;
    const int lane = tid & 31;
    const int wid  = tid >> 5;

    // ---------------- Phase 1 ----------------
    if (bid < 72) {
        const int jt = bid / 8, ic = bid % 8;
        const int i0 = ic * 64;
        const int j  = jt * 64 + tx;

        for (int q = tid; q < 16 * 64; q += 256) {
            const int b = q >> 6, il = q & 63;
            sfc[q] = Fc[b * FC_DIM + i0 + il];
        }
        __syncthreads();

        float w[16];
        const float* __restrict__ wp = W1 + (size_t)(i0 + ty * 16) * CKK + j;
        #pragma unroll
        for (int k = 0; k < 16; ++k) w[k] = __ldg(wp + k * CKK);

        float acc[16];
        #pragma unroll
        for (int b = 0; b < 16; ++b) acc[b] = 0.f;
        #pragma unroll
        for (int k = 0; k < 16; ++k) {
            const int il = ty * 16 + k;
            #pragma unroll
            for (int b = 0; b < 16; ++b)
                acc[b] = fmaf(sfc[b * 64 + il], w[k], acc[b]);
        }
        #pragma unroll
        for (int b = 0; b < 16; ++b) srd[(ty * 64 + tx) * 16 + b] = acc[b];
        __syncthreads();

        for (int q = tid; q < 1024; q += 256) {
            const int jj = q >> 4, b = q & 15;
            float v = ((srd[(jj) * 16 + b]       + srd[(64 + jj) * 16 + b]) +
                       (srd[(128 + jj) * 16 + b] + srd[(192 + jj) * 16 + b]));
            if (ic == 0) v += b1[jt * 64 + jj];
            g_p1[ic][b * CKK + jt * 64 + jj] = v;
        }
    }

    grid_barrier(&g_c1, 0);

    // ---------------- Phase 2 ----------------
    {
        const int jt = bid / 9, ic = bid % 9;
        const int i0 = ic * 64;
        const int j  = jt * 64 + tx;

        for (int q = tid; q < 16 * 64; q += 256) {
            const int b = q >> 6, il = q & 63;
            const int idx = b * CKK + i0 + il;
            float h = (((g_p1[0][idx] + g_p1[1][idx]) + (g_p1[2][idx] + g_p1[3][idx])) +
                       ((g_p1[4][idx] + g_p1[5][idx]) + (g_p1[6][idx] + g_p1[7][idx])));
            sfc[q] = fmaxf(h, 0.0f);
        }
        __syncthreads();

        float w[16];
        const float* __restrict__ wp = W2 + (size_t)(i0 + ty * 16) * CKK + j;
        #pragma unroll
        for (int k = 0; k < 16; ++k) w[k] = __ldg(wp + k * CKK);

        float acc[16];
        #pragma unroll
        for (int b = 0; b < 16; ++b) acc[b] = 0.f;
        #pragma unroll
        for (int k = 0; k < 16; ++k) {
            const int il = ty * 16 + k;
            #pragma unroll
            for (int b = 0; b < 16; ++b)
                acc[b] = fmaf(sfc[b * 64 + il], w[k], acc[b]);
        }
        __syncthreads();
        #pragma unroll
        for (int b = 0; b < 16; ++b) srd[(ty * 64 + tx) * 16 + b] = acc[b];
        __syncthreads();

        for (int q = tid; q < 1024; q += 256) {
            const int jj = q >> 4, b = q & 15;
            float v = ((srd[(jj) * 16 + b]       + srd[(64 + jj) * 16 + b]) +
                       (srd[(128 + jj) * 16 + b] + srd[(192 + jj) * 16 + b]));
            if (ic == 0) v += b2[jt * 64 + jj];
            g_p2[ic][b * CKK + jt * 64 + jj] = v;
        }
    }

    grid_barrier(&g_c2, &g_c1);   // last arriver resets c1 for next replay

    // ---------------- Phase 3: softmax (blocks 0..15) ----------------
    if (bid < B_SZ) {
        const int b = bid;
        float lg[3];
        float lmax = -INFINITY;
        #pragma unroll
        for (int t = 0; t < 3; ++t) {
            if (t < 2 || tid < 64) {
                const int idx = b * CKK + tid + 256 * t;
                float v = (((g_p2[0][idx] + g_p2[1][idx]) + (g_p2[2][idx] + g_p2[3][idx])) +
                           ((g_p2[4][idx] + g_p2[5][idx]) + (g_p2[6][idx] + g_p2[7][idx])) +
                           g_p2[8][idx]);
                lg[t] = v;
                lmax = fmaxf(lmax, v);
            } else lg[t] = -INFINITY;
        }
        #pragma unroll
        for (int o = 16; o > 0; o >>= 1)
            lmax = fmaxf(lmax, __shfl_xor_sync(0xffffffffu, lmax, o));
        if (lane == 0) red[wid] = lmax;
        __syncthreads();
        if (wid == 0) {
            float v = (lane < 8) ? red[lane] : -INFINITY;
            #pragma unroll
            for (int o = 4; o > 0; o >>= 1)
                v = fmaxf(v, __shfl_xor_sync(0xffffffffu, v, o));
            if (lane == 0) bcast = v;
        }
        __syncthreads();
        const float maxv = bcast;

        float e[3];
        float lsum = 0.f;
        #pragma unroll
        for (int t = 0; t < 3; ++t) {
            e[t] = (t < 2 || tid < 64) ? expf(lg[t] - maxv) : 0.0f;
            lsum += e[t];
        }
        #pragma unroll
        for (int o = 16; o > 0; o >>= 1)
            lsum += __shfl_xor_sync(0xffffffffu, lsum, o);
        __syncthreads();
        if (lane == 0) red[wid] = lsum;
        __syncthreads();
        if (wid == 0) {
            float v = (lane < 8) ? red[lane] : 0.0f;
            #pragma unroll
            for (int o = 4; o > 0; o >>= 1)
                v += __shfl_xor_sync(0xffffffffu, v, o);
            if (lane == 0) bcast = v;
        }
        __syncthreads();
        const float inv = 1.0f / bcast;

        #pragma unroll
        for (int t = 0; t < 3; ++t) {
            if (t < 2 || tid < 64) {
                const int idx = b * CKK + tid + 256 * t;
                const float kw = e[t] * inv;
                g_kw[idx] = kw;
                if (write_tail) kw_tail[idx] = kw;
            }
        }
    }

    // Exit barrier (arrive-only): last arriver resets c2 and c3.
    __threadfence();
    __syncthreads();
    if (tid == 0) {
        unsigned int old = atomicAdd(&g_c3, 1u);
        if (old == MLP_BLOCKS - 1u) { g_c2 = 0u; g_c3 = 0u; __threadfence(); }
    }
}

// ---------------------------------------------------------------------------
// Depthwise 3x3 conv (verbatim measured-best), launched with PDL:
// prefetch two window rows, hardware-wait on MLP grid completion, compute.
// Block 256: tx 0..63 (float4 col group), ty 0..3 (8-row strip). Grid (8,1024).
// ---------------------------------------------------------------------------
#define ROWS_PER_BLOCK 32
#define ROWS_PER_THREAD 8

__device__ __forceinline__ void load_row6(
    const float* __restrict__ img, int gr, int tx, float* __restrict__ w)
{
    gr = (gr < 0) ? 1 : ((gr > HH - 1) ? (2 * HH - 2 - gr) : gr);
    const float* rowp = img + gr * WW;
    const float4 q = __ldg((const float4*)rowp + tx);
    w[1] = q.x; w[2] = q.y; w[3] = q.z; w[4] = q.w;
    w[0] = (tx == 0)      ? q.y : __ldg(rowp + 4 * tx - 1);
    w[5] = (tx == WW/4-1) ? q.z : __ldg(rowp + 4 * tx + 4);
}

__global__ __launch_bounds__(256) void EKG_conv_kernel(
    const float* __restrict__ Fd,
    float* __restrict__ out)
{
    const int bc   = blockIdx.y;
    const int tid  = threadIdx.x;
    const int tx   = tid & 63;
    const int ty   = tid >> 6;
    const int rbase = blockIdx.x * ROWS_PER_BLOCK + ty * ROWS_PER_THREAD;

    const float* __restrict__ img = Fd  + (size_t)bc * IMG_PIX;
    float*       __restrict__ o   = out + (size_t)bc * IMG_PIX;

    // Prefetch first two window rows (independent of the MLP output).
    float win[3][6];
    load_row6(img, rbase - 1, tx, win[0]);
    load_row6(img, rbase + 0, tx, win[1]);

    // Hardware wait: all writes of the preceding (MLP) grid become visible.
    asm volatile("griddepcontrol.wait;" ::: "memory");

    const float* kwp = g_kw + bc * 9;
    const float w00 = __ldg(kwp+0), w01 = __ldg(kwp+1), w02 = __ldg(kwp+2);
    const float w10 = __ldg(kwp+3), w11 = __ldg(kwp+4), w12 = __ldg(kwp+5);
    const float w20 = __ldg(kwp+6), w21 = __ldg(kwp+7), w22 = __ldg(kwp+8);

    #pragma unroll
    for (int rr = 0; rr < ROWS_PER_THREAD; ++rr) {
        load_row6(img, rbase + rr + 1, tx, win[(rr + 2) % 3]);

        const float* T  = win[rr % 3];
        const float* M  = win[(rr + 1) % 3];
        const float* Bt = win[(rr + 2) % 3];

        float4 r;
        r.x = w00*T[0]; r.x = fmaf(w01,T[1],r.x); r.x = fmaf(w02,T[2],r.x);
        r.x = fmaf(w10,M[0],r.x); r.x = fmaf(w11,M[1],r.x); r.x = fmaf(w12,M[2],r.x);
        r.x = fmaf(w20,Bt[0],r.x); r.x = fmaf(w21,Bt[1],r.x); r.x = fmaf(w22,Bt[2],r.x);

        r.y = w00*T[1]; r.y = fmaf(w01,T[2],r.y); r.y = fmaf(w02,T[3],r.y);
        r.y = fmaf(w10,M[1],r.y); r.y = fmaf(w11,M[2],r.y); r.y = fmaf(w12,M[3],r.y);
        r.y = fmaf(w20,Bt[1],r.y); r.y = fmaf(w21,Bt[2],r.y); r.y = fmaf(w22,Bt[3],r.y);

        r.z = w00*T[2]; r.z = fmaf(w01,T[3],r.z); r.z = fmaf(w02,T[4],r.z);
        r.z = fmaf(w10,M[2],r.z); r.z = fmaf(w11,M[3],r.z); r.z = fmaf(w12,M[4],r.z);
        r.z = fmaf(w20,Bt[2],r.z); r.z = fmaf(w21,Bt[3],r.z); r.z = fmaf(w22,Bt[4],r.z);

        r.w = w00*T[3]; r.w = fmaf(w01,T[4],r.w); r.w = fmaf(w02,T[5],r.w);
        r.w = fmaf(w10,M[3],r.w); r.w = fmaf(w11,M[4],r.w); r.w = fmaf(w12,M[5],r.w);
        r.w = fmaf(w20,Bt[3],r.w); r.w = fmaf(w21,Bt[4],r.w); r.w = fmaf(w22,Bt[5],r.w);

        __stcs((float4*)(o + (size_t)(rbase + rr) * WW + 4 * tx), r);
    }
}

// ---------------------------------------------------------------------------
extern "C" void kernel_launch(void* const* d_in, const int* in_sizes, int n_in,
                              void* d_out, int out_size) {
    const float* Fd = (const float*)d_in[0];
    const float* Fc = (const float*)d_in[1];
    const float* W1 = (const float*)d_in[2];
    const float* b1 = (const float*)d_in[3];
    const float* W2 = (const float*)d_in[4];
    const float* b2 = (const float*)d_in[5];
    float* out = (float*)d_out;

    const int write_tail = ((size_t)out_size >= FOUT_ELEMS + (size_t)B_SZ * CKK) ? 1 : 0;
    float* kw_tail = out + FOUT_ELEMS;

    EKG_mlp_one<<<MLP_BLOCKS, 256>>>(Fc, W1, b1, W2, b2, kw_tail, write_tail);

    // Conv launched as a programmatic dependent of the MLP kernel.
    cudaLaunchConfig_t cfg = {};
    cfg.gridDim  = dim3(HH / ROWS_PER_BLOCK, N_IMG, 1);
    cfg.blockDim = dim3(256, 1, 1);
    cfg.dynamicSmemBytes = 0;
    cfg.stream = 0;
    cudaLaunchAttribute attr[1];
    attr[0].id = cudaLaunchAttributeProgrammaticStreamSerialization;
    attr[0].val.programmaticStreamSerializationAllowed = 1;
    cfg.attrs = attr;
    cfg.numAttrs = 1;
    cudaLaunchKernelEx(&cfg, EKG_conv_kernel, Fd, out);
}